// round 13
// baseline (speedup 1.0000x reference)
#include <cuda_runtime.h>
#include <cuda_fp16.h>
#include <stdint.h>

// ---------------- problem constants ----------------
#define KDIM    41024
#define NHID    256
#define MTOT    4096          // 2048 white + 2048 black
#define NTILES  32            // m-tiles of 128 rows
#define CPT     641           // BK64 chunks per m-tile (41024/64)
#define TOTCH   (NTILES * CPT)  // 20512
#define NCTAS   148
#define WCHUNK  139           // ceil(20512/148)
#define NSLOTS  6

// GEMM tile: BM=128, BN=256, BK=64 (f16), 512 threads, 4-stage pipeline
#define BK          64
#define PITCH_U     36        // u32 per row: 32 data (64 f16) + 4 pad
#define PITCH_BY    144
#define A_U32       (128 * PITCH_U)            // 4608
#define B_U32       (256 * PITCH_U)            // 9216
#define STAGE_U32   (A_U32 + B_U32)            // 13824
#define STAGE_BYTES (STAGE_U32 * 4)            // 55296
#define A_BYTES     (A_U32 * 4)                // 18432
#define GEMM_SMEM   (4 * STAGE_BYTES)          // 221184 (1 CTA/SM, fits 227KB)
// tail smem: Wh1T[512*33] + c_sm[8*512] + Wh2T[32*33] + x1p[16*32] + x1s[8*32]
#define TAIL_SMEM   ((512*33 + 8*512 + 32*33 + 16*32 + 8*32) * 4)  // ~91KB

// partial slots: [6][4096][256] fp32 = 25.2MB static scratch.
// Zero-initialized at module load; slots >= cnt(tile) are NEVER written,
// so they remain zero across all launches -> fixed 6-way reduce is exact.
__device__ float g_part[(size_t)NSLOTS * MTOT * NHID];

// ---------------- helpers ----------------
__device__ __forceinline__ uint32_t f2h2(float lo, float hi) {
    uint32_t r; asm("cvt.rn.f16x2.f32 %0, %1, %2;" : "=r"(r) : "f"(hi), "f"(lo)); return r;
}
__device__ __forceinline__ uint2 cvt4h(float4 v) {
    uint2 o; o.x = f2h2(v.x, v.y); o.y = f2h2(v.z, v.w); return o;
}
__device__ __forceinline__ void mma_f16(float* c, const uint32_t* a, const uint32_t* b) {
    asm volatile(
        "mma.sync.aligned.m16n8k16.row.col.f32.f16.f16.f32 "
        "{%0,%1,%2,%3}, {%4,%5,%6,%7}, {%8,%9}, {%0,%1,%2,%3};"
        : "+f"(c[0]), "+f"(c[1]), "+f"(c[2]), "+f"(c[3])
        : "r"(a[0]), "r"(a[1]), "r"(a[2]), "r"(a[3]), "r"(b[0]), "r"(b[1]));
}
__device__ __forceinline__ void ldsm_x4(uint32_t* r, uint32_t addr) {
    asm volatile("ldmatrix.sync.aligned.m8n8.x4.shared.b16 {%0,%1,%2,%3}, [%4];"
        : "=r"(r[0]), "=r"(r[1]), "=r"(r[2]), "=r"(r[3]) : "r"(addr));
}

// =====================================================================
// Kernel 1: flat-balanced GEMM. 148 CTAs; CTA c covers global chunk
// range [139c, 139c+139). A range spans <=2 m-tiles; per tile-segment
// the CTA accumulates and flushes a partial to slot=ordinal-in-tile.
// 4-stage smem pipeline: iteration l computes stage l&3 and loads chunk
// l+2 into stage (l+2)&3; ONE barrier per 2 chunks (after odd l).
// Chunk c: loaded at iter c-2, consumed at iter c; exactly one of
// {c-2, c-1} is odd -> exactly one barrier separates store/load (RAW ok,
// and the stage-reuse WAR read@l-2/write@l is covered by the same one).
// =====================================================================
__global__ void __launch_bounds__(512, 1) nnue_gemm(
    const float* __restrict__ wf, const float* __restrict__ bfeat,
    const float* __restrict__ W_in)
{
    extern __shared__ uint32_t smem[];
    const uint32_t sbase = (uint32_t)__cvta_generic_to_shared(smem);

    const int tid = threadIdx.x;
    const int wid = tid >> 5;
    const int lane = tid & 31;
    const int lr = lane >> 2;       // 0..7
    const int lc = lane & 3;        // 0..3
    const int mw = (wid & 3) * 32;  // 4 m-warps
    const int nw = (wid >> 2) * 64; // 4 n-warps

    const int cta = blockIdx.x;
    int g0 = cta * WCHUNK;
    const int gEnd = min(g0 + WCHUNK, TOTCH);
    if (g0 >= gEnd) return;

    // ------ producer mapping: A 4 float4/thread, B 8 float4/thread ------
    const int pr = tid >> 4;        // 0..31 row base
    const int pc = tid & 15;        // float4 col 0..15 (64 floats per row)
    const int sA0 = pr * PITCH_U + 2 * pc;                 // u32 index
    const int sB0 = A_U32 + pr * PITCH_U + 2 * pc;
    const size_t QSTEP = (size_t)32 * KDIM;                // +32 rows per q
    const float* pB0 = W_in + (size_t)pr * KDIM + pc * 4;

    // ------ ldmatrix lane addresses ------
    const uint32_t aAddr = sbase + (uint32_t)(mw + (lane & 15)) * PITCH_BY
                         + (uint32_t)((lane >> 4) << 4);
    const uint32_t bAddr = sbase + A_BYTES + (uint32_t)(nw + (lane & 7)) * PITCH_BY
                         + (uint32_t)(((lane >> 3) & 3) << 4);

    float acc[2][8][4];

    // ---------------- segment loop (<=2 iterations) ----------------
    while (g0 < gEnd) {
        const int t = g0 / CPT;                       // m-tile
        const int seg_end = min(gEnd, (t + 1) * CPT);
        const int nch = seg_end - g0;
        const int kbase = g0 - t * CPT;               // first chunk within tile
        const int ordinal = cta - (t * CPT) / WCHUNK; // partial slot, 0..5

        const float* Xb = (t < 16) ? (wf + (size_t)t * 128 * KDIM)
                                   : (bfeat + (size_t)(t - 16) * 128 * KDIM);
        const float* pA0 = Xb + (size_t)pr * KDIM + pc * 4;

        #pragma unroll
        for (int i = 0; i < 2; i++)
            #pragma unroll
            for (int tt = 0; tt < 8; tt++)
                #pragma unroll
                for (int q = 0; q < 4; q++) acc[i][tt][q] = 0.0f;

        // prologue: fill stage 0 (chunk kbase) and stage 1 (chunk kbase+1)
        {
            size_t k = (size_t)kbase * BK;
            #pragma unroll
            for (int q = 0; q < 4; q++)
                *(uint2*)(smem + sA0 + q * 32 * PITCH_U) = cvt4h(*(const float4*)(pA0 + q * QSTEP + k));
            #pragma unroll
            for (int q = 0; q < 8; q++)
                *(uint2*)(smem + sB0 + q * 32 * PITCH_U) = cvt4h(*(const float4*)(pB0 + q * QSTEP + k));
            if (nch > 1) {
                size_t k1 = k + BK;
                #pragma unroll
                for (int q = 0; q < 4; q++)
                    *(uint2*)(smem + STAGE_U32 + sA0 + q * 32 * PITCH_U) = cvt4h(*(const float4*)(pA0 + q * QSTEP + k1));
                #pragma unroll
                for (int q = 0; q < 8; q++)
                    *(uint2*)(smem + STAGE_U32 + sB0 + q * 32 * PITCH_U) = cvt4h(*(const float4*)(pB0 + q * QSTEP + k1));
            }
        }
        __syncthreads();

        for (int l = 0; l < nch; l++) {
            const bool more = (l + 2 < nch);
            const uint32_t stOff = (uint32_t)(l & 3) * STAGE_BYTES;
            const uint32_t nbU32 = (uint32_t)((l + 2) & 3) * STAGE_U32;
            const size_t k2 = (size_t)(kbase + l + 2) * BK;

            // batch 1: A(4) + B(q=0,1) loads for chunk l+2
            float4 v0, v1, v2, v3, v4, v5;
            if (more) {
                v0 = *(const float4*)(pA0 + 0 * QSTEP + k2);
                v1 = *(const float4*)(pA0 + 1 * QSTEP + k2);
                v2 = *(const float4*)(pA0 + 2 * QSTEP + k2);
                v3 = *(const float4*)(pA0 + 3 * QSTEP + k2);
                v4 = *(const float4*)(pB0 + 0 * QSTEP + k2);
                v5 = *(const float4*)(pB0 + 1 * QSTEP + k2);
            }

            #pragma unroll
            for (int jp = 0; jp < 2; jp++) {     // 2 k-step pairs (each 32 f16)
                uint32_t aF[2][2][4];
                #pragma unroll
                for (int i = 0; i < 2; i++)
                    #pragma unroll
                    for (int js = 0; js < 2; js++)
                        ldsm_x4(aF[i][js], aAddr + stOff
                                + (uint32_t)(i * 16 * PITCH_BY + jp * 64 + js * 32));

                uint32_t bF[2][4];
                ldsm_x4(bF[0], bAddr + stOff + (uint32_t)(jp * 64));
                #pragma unroll
                for (int tt = 0; tt < 8; tt++) {
                    if (tt < 7)
                        ldsm_x4(bF[(tt + 1) & 1], bAddr + stOff
                                + (uint32_t)((tt + 1) * 8 * PITCH_BY + jp * 64));
                    const uint32_t* bf = bF[tt & 1];
                    mma_f16(acc[0][tt], aF[0][0], bf);       // k-step 2jp
                    mma_f16(acc[1][tt], aF[1][0], bf);
                    mma_f16(acc[0][tt], aF[0][1], bf + 2);   // k-step 2jp+1
                    mma_f16(acc[1][tt], aF[1][1], bf + 2);
                }

                if (jp == 0 && more) {
                    *(uint2*)(smem + nbU32 + sA0 + 0 * 32 * PITCH_U) = cvt4h(v0);
                    *(uint2*)(smem + nbU32 + sA0 + 1 * 32 * PITCH_U) = cvt4h(v1);
                    *(uint2*)(smem + nbU32 + sA0 + 2 * 32 * PITCH_U) = cvt4h(v2);
                    *(uint2*)(smem + nbU32 + sA0 + 3 * 32 * PITCH_U) = cvt4h(v3);
                    *(uint2*)(smem + nbU32 + sB0 + 0 * 32 * PITCH_U) = cvt4h(v4);
                    *(uint2*)(smem + nbU32 + sB0 + 1 * 32 * PITCH_U) = cvt4h(v5);
                    v0 = *(const float4*)(pB0 + 2 * QSTEP + k2);
                    v1 = *(const float4*)(pB0 + 3 * QSTEP + k2);
                    v2 = *(const float4*)(pB0 + 4 * QSTEP + k2);
                    v3 = *(const float4*)(pB0 + 5 * QSTEP + k2);
                    v4 = *(const float4*)(pB0 + 6 * QSTEP + k2);
                    v5 = *(const float4*)(pB0 + 7 * QSTEP + k2);
                }
            }

            if (more) {
                *(uint2*)(smem + nbU32 + sB0 + 2 * 32 * PITCH_U) = cvt4h(v0);
                *(uint2*)(smem + nbU32 + sB0 + 3 * 32 * PITCH_U) = cvt4h(v1);
                *(uint2*)(smem + nbU32 + sB0 + 4 * 32 * PITCH_U) = cvt4h(v2);
                *(uint2*)(smem + nbU32 + sB0 + 5 * 32 * PITCH_U) = cvt4h(v3);
                *(uint2*)(smem + nbU32 + sB0 + 6 * 32 * PITCH_U) = cvt4h(v4);
                *(uint2*)(smem + nbU32 + sB0 + 7 * 32 * PITCH_U) = cvt4h(v5);
            }
            if (l & 1) __syncthreads();   // one barrier per 2 chunks
        }
        __syncthreads();   // segment end: cover odd-nch tail + stage reuse

        // ------ flush partial for this segment ------
        float* op = g_part + ((size_t)ordinal * MTOT + (size_t)t * 128) * NHID;
        #pragma unroll
        for (int i = 0; i < 2; i++) {
            #pragma unroll
            for (int tt = 0; tt < 8; tt++) {
                int row = mw + i * 16 + lr;
                int col = nw + tt * 8 + 2 * lc;
                float2 w0 = make_float2(acc[i][tt][0], acc[i][tt][1]);
                float2 w1 = make_float2(acc[i][tt][2], acc[i][tt][3]);
                *(float2*)(op + (size_t)row * NHID + col) = w0;
                *(float2*)(op + (size_t)(row + 8) * NHID + col) = w1;
            }
        }

        g0 = seg_end;
    }
}

// =====================================================================
// Kernel 2: fixed 6-slot reduce + bias + relu + 3-layer MLP tail
// 256 blocks x 512 threads, 8 batch rows per block.
// Layer 1 split: warp w -> row (w&7), j-half (w>>3); partials combined
// through smem. smem ~91KB -> 2 blocks/SM co-resident.
// =====================================================================
__global__ void __launch_bounds__(512) nnue_tail(
    const float* __restrict__ b_in,
    const float* __restrict__ W_h1, const float* __restrict__ b_h1,
    const float* __restrict__ W_h2, const float* __restrict__ b_h2,
    const float* __restrict__ W_out, const float* __restrict__ b_out,
    float* __restrict__ out)
{
    extern __shared__ float smem_t[];
    float* Wh1T = smem_t;                    // [512][33]
    float* c_sm = Wh1T + 512 * 33;           // [8][512]
    float* Wh2T = c_sm + 8 * 512;            // [32][33]
    float* x1p  = Wh2T + 32 * 33;            // [16][32] layer-1 partials
    float* x1s  = x1p + 16 * 32;             // [8][32]

    const int tid = threadIdx.x;
    const int row0 = blockIdx.x * 8;         // 0..2040

    for (int i = tid; i < 512 * 32; i += 512) {
        int o = i >> 9, j = i & 511;
        Wh1T[j * 33 + o] = W_h1[i];
    }
    for (int i = tid; i < 32 * 32; i += 512) {   // 1024 elems, 2 iters
        int o = i >> 5, j = i & 31;
        Wh2T[j * 33 + o] = W_h2[i];
    }
    // combined = [relu(wh), relu(bh)]: fixed 6-slot reduce (unwritten slots
    // are guaranteed-zero __device__ memory) -> 6 independent loads in flight
    for (int e = tid; e < 8 * 512; e += 512) {
        int rs = e >> 9, j = e & 511;
        int col = j & 255;
        int m = (j < 256) ? (row0 + rs) : (2048 + row0 + rs);
        size_t base = (size_t)m * NHID + col;
        float p0 = g_part[0 * (size_t)MTOT * NHID + base];
        float p1 = g_part[1 * (size_t)MTOT * NHID + base];
        float p2 = g_part[2 * (size_t)MTOT * NHID + base];
        float p3 = g_part[3 * (size_t)MTOT * NHID + base];
        float p4 = g_part[4 * (size_t)MTOT * NHID + base];
        float p5 = g_part[5 * (size_t)MTOT * NHID + base];
        float v = b_in[col] + ((p0 + p1) + (p2 + p3)) + (p4 + p5);
        c_sm[e] = fmaxf(v, 0.0f);
    }
    __syncthreads();

    const int o    = tid & 31;
    const int w    = tid >> 5;       // 0..15
    const int r    = w & 7;          // batch row within block
    const int half = w >> 3;         // j-range half: 0 or 1

    // layer 1 (split): 256 js per warp, c loads vectorized
    {
        float a0 = 0.f, a1 = 0.f, a2 = 0.f, a3 = 0.f;
        const float* c = c_sm + r * 512 + half * 256;
        #pragma unroll 2
        for (int j = 0; j < 256; j += 4) {
            float4 cv = *(const float4*)(c + j);
            int jw = half * 256 + j;
            a0 = fmaf(cv.x, Wh1T[(jw + 0) * 33 + o], a0);
            a1 = fmaf(cv.y, Wh1T[(jw + 1) * 33 + o], a1);
            a2 = fmaf(cv.z, Wh1T[(jw + 2) * 33 + o], a2);
            a3 = fmaf(cv.w, Wh1T[(jw + 3) * 33 + o], a3);
        }
        x1p[(half * 8 + r) * 32 + o] = (a0 + a1) + (a2 + a3);
    }
    __syncthreads();

    if (w < 8) {   // warps 0-7: combine halves, layer 2, output
        float x1 = fmaxf(x1p[r * 32 + o] + x1p[(8 + r) * 32 + o] + b_h1[o], 0.0f);
        x1s[r * 32 + o] = x1;
        __syncwarp();

        // layer 2: [32, 32]
        float acc2 = b_h2[o];
        #pragma unroll
        for (int j = 0; j < 32; j++)
            acc2 = fmaf(x1s[r * 32 + j], Wh2T[j * 33 + o], acc2);
        float x2 = fmaxf(acc2, 0.0f);

        // output: dot + warp reduce
        float y = x2 * W_out[o];
        #pragma unroll
        for (int d = 16; d > 0; d >>= 1)
            y += __shfl_xor_sync(0xFFFFFFFF, y, d);
        if (o == 0)
            out[row0 + r] = y + b_out[0];
    }
}

// =====================================================================
extern "C" void kernel_launch(void* const* d_in, const int* in_sizes, int n_in,
                              void* d_out, int out_size) {
    const float* wf    = (const float*)d_in[0];
    const float* bfeat = (const float*)d_in[1];
    const float* W_in  = (const float*)d_in[2];
    const float* b_in  = (const float*)d_in[3];
    const float* W_h1  = (const float*)d_in[4];
    const float* b_h1  = (const float*)d_in[5];
    const float* W_h2  = (const float*)d_in[6];
    const float* b_h2  = (const float*)d_in[7];
    const float* W_out = (const float*)d_in[8];
    const float* b_out = (const float*)d_in[9];
    float* out = (float*)d_out;

    cudaFuncSetAttribute(nnue_gemm, cudaFuncAttributeMaxDynamicSharedMemorySize, GEMM_SMEM);
    cudaFuncSetAttribute(nnue_tail, cudaFuncAttributeMaxDynamicSharedMemorySize, TAIL_SMEM);

    nnue_gemm<<<NCTAS, 512, GEMM_SMEM>>>(wf, bfeat, W_in);
    nnue_tail<<<256, 512, TAIL_SMEM>>>(b_in, W_h1, b_h1, W_h2, b_h2, W_out, b_out, out);
}

// round 14
// speedup vs baseline: 1.1760x; 1.1760x over previous
#include <cuda_runtime.h>
#include <cuda_fp16.h>
#include <stdint.h>

// ---------------- problem constants ----------------
#define KDIM    41024
#define NHID    256
#define MTOT    4096          // 2048 white + 2048 black
#define NTILES  32            // m-tiles of 128 rows
#define CPT     641           // BK64 chunks per m-tile (41024/64)
#define TOTCH   (NTILES * CPT)  // 20512
#define NCTAS   148
#define WCHUNK  139           // ceil(20512/148)
#define NSLOTS  6

// GEMM tile: BM=128, BN=256, BK=64 (f16), 512 threads, 3-stage pipeline
#define BK          64
#define PITCH_U     36        // u32 per row: 32 data (64 f16) + 4 pad
#define PITCH_BY    144
#define A_U32       (128 * PITCH_U)            // 4608
#define B_U32       (256 * PITCH_U)            // 9216
#define STAGE_U32   (A_U32 + B_U32)            // 13824
#define STAGE_BYTES (STAGE_U32 * 4)            // 55296
#define A_BYTES     (A_U32 * 4)                // 18432
#define GEMM_SMEM   (3 * STAGE_BYTES)          // 165888 (1 CTA/SM)
// tail smem: Wh1T[512*33] + c_sm[8*512] + Wh2T[32*33] + x1p[16*32] + x1s[8*32]
#define TAIL_SMEM   ((512*33 + 8*512 + 32*33 + 16*32 + 8*32) * 4)  // ~91KB

// partial slots: [6][4096][256] fp32 = 25.2MB static scratch.
// Zero-initialized at module load; slots >= cnt(tile) are NEVER written,
// so they remain zero across all launches -> fixed 6-way reduce is exact.
__device__ float g_part[(size_t)NSLOTS * MTOT * NHID];

// ---------------- helpers ----------------
__device__ __forceinline__ uint32_t f2h2(float lo, float hi) {
    uint32_t r; asm("cvt.rn.f16x2.f32 %0, %1, %2;" : "=r"(r) : "f"(hi), "f"(lo)); return r;
}
__device__ __forceinline__ uint2 cvt4h(float4 v) {
    uint2 o; o.x = f2h2(v.x, v.y); o.y = f2h2(v.z, v.w); return o;
}
__device__ __forceinline__ void mma_f16(float* c, const uint32_t* a, const uint32_t* b) {
    asm volatile(
        "mma.sync.aligned.m16n8k16.row.col.f32.f16.f16.f32 "
        "{%0,%1,%2,%3}, {%4,%5,%6,%7}, {%8,%9}, {%0,%1,%2,%3};"
        : "+f"(c[0]), "+f"(c[1]), "+f"(c[2]), "+f"(c[3])
        : "r"(a[0]), "r"(a[1]), "r"(a[2]), "r"(a[3]), "r"(b[0]), "r"(b[1]));
}
__device__ __forceinline__ void ldsm_x4(uint32_t* r, uint32_t addr) {
    asm volatile("ldmatrix.sync.aligned.m8n8.x4.shared.b16 {%0,%1,%2,%3}, [%4];"
        : "=r"(r[0]), "=r"(r[1]), "=r"(r[2]), "=r"(r[3]) : "r"(addr));
}

// =====================================================================
// Kernel 1: flat-balanced GEMM. 148 CTAs; CTA c covers global chunk
// range [139c, 139c+139). A range spans <=2 m-tiles; per tile-segment
// the CTA accumulates and flushes a partial to slot=ordinal-in-tile.
// 3-stage smem pipeline, distance-2 prefetch, ONE barrier per chunk
// (unconditional, loop end — R13 showed the per-iter barrier is
// load-bearing for warp phase-lock + ptxas scheduling).
// RAW: chunk c written @iter c-2, read @iter c (2 barriers between).
// WAR: stage (l+2)%3 == (l-1)%3 last read @iter l-1 (1 barrier between).
// =====================================================================
__global__ void __launch_bounds__(512, 1) nnue_gemm(
    const float* __restrict__ wf, const float* __restrict__ bfeat,
    const float* __restrict__ W_in)
{
    extern __shared__ uint32_t smem[];
    const uint32_t sbase = (uint32_t)__cvta_generic_to_shared(smem);

    const int tid = threadIdx.x;
    const int wid = tid >> 5;
    const int lane = tid & 31;
    const int lr = lane >> 2;       // 0..7
    const int lc = lane & 3;        // 0..3
    const int mw = (wid & 3) * 32;  // 4 m-warps
    const int nw = (wid >> 2) * 64; // 4 n-warps

    const int cta = blockIdx.x;
    int g0 = cta * WCHUNK;
    const int gEnd = min(g0 + WCHUNK, TOTCH);
    if (g0 >= gEnd) return;

    // ------ producer mapping: A 4 float4/thread, B 8 float4/thread ------
    const int pr = tid >> 4;        // 0..31 row base
    const int pc = tid & 15;        // float4 col 0..15 (64 floats per row)
    const int sA0 = pr * PITCH_U + 2 * pc;                 // u32 index
    const int sB0 = A_U32 + pr * PITCH_U + 2 * pc;
    const size_t QSTEP = (size_t)32 * KDIM;                // +32 rows per q
    const float* pB0 = W_in + (size_t)pr * KDIM + pc * 4;

    // ------ ldmatrix lane addresses ------
    const uint32_t aAddr = sbase + (uint32_t)(mw + (lane & 15)) * PITCH_BY
                         + (uint32_t)((lane >> 4) << 4);
    const uint32_t bAddr = sbase + A_BYTES + (uint32_t)(nw + (lane & 7)) * PITCH_BY
                         + (uint32_t)(((lane >> 3) & 3) << 4);

    float acc[2][8][4];

    // ---------------- segment loop (<=2 iterations) ----------------
    while (g0 < gEnd) {
        const int t = g0 / CPT;                       // m-tile
        const int seg_end = min(gEnd, (t + 1) * CPT);
        const int nch = seg_end - g0;
        const int kbase = g0 - t * CPT;               // first chunk within tile
        const int ordinal = cta - (t * CPT) / WCHUNK; // partial slot, 0..5

        const float* Xb = (t < 16) ? (wf + (size_t)t * 128 * KDIM)
                                   : (bfeat + (size_t)(t - 16) * 128 * KDIM);
        const float* pA0 = Xb + (size_t)pr * KDIM + pc * 4;

        #pragma unroll
        for (int i = 0; i < 2; i++)
            #pragma unroll
            for (int tt = 0; tt < 8; tt++)
                #pragma unroll
                for (int q = 0; q < 4; q++) acc[i][tt][q] = 0.0f;

        // prologue: fill stage 0 (chunk kbase) and stage 1 (chunk kbase+1)
        {
            size_t k = (size_t)kbase * BK;
            #pragma unroll
            for (int q = 0; q < 4; q++)
                *(uint2*)(smem + sA0 + q * 32 * PITCH_U) = cvt4h(*(const float4*)(pA0 + q * QSTEP + k));
            #pragma unroll
            for (int q = 0; q < 8; q++)
                *(uint2*)(smem + sB0 + q * 32 * PITCH_U) = cvt4h(*(const float4*)(pB0 + q * QSTEP + k));
            if (nch > 1) {
                size_t k1 = k + BK;
                #pragma unroll
                for (int q = 0; q < 4; q++)
                    *(uint2*)(smem + STAGE_U32 + sA0 + q * 32 * PITCH_U) = cvt4h(*(const float4*)(pA0 + q * QSTEP + k1));
                #pragma unroll
                for (int q = 0; q < 8; q++)
                    *(uint2*)(smem + STAGE_U32 + sB0 + q * 32 * PITCH_U) = cvt4h(*(const float4*)(pB0 + q * QSTEP + k1));
            }
        }
        __syncthreads();

        int cs = 0;   // l % 3 (compute stage), maintained without division
        for (int l = 0; l < nch; l++) {
            const bool more = (l + 2 < nch);
            const int ws = (cs == 0) ? 2 : cs - 1;     // (l+2)%3 == (l-1)%3
            const uint32_t stOff = (uint32_t)cs * STAGE_BYTES;
            const uint32_t nbU32 = (uint32_t)ws * STAGE_U32;
            const size_t k2 = (size_t)(kbase + l + 2) * BK;

            // batch 1: A(4) + B(q=0,1) loads for chunk l+2
            float4 v0, v1, v2, v3, v4, v5;
            if (more) {
                v0 = *(const float4*)(pA0 + 0 * QSTEP + k2);
                v1 = *(const float4*)(pA0 + 1 * QSTEP + k2);
                v2 = *(const float4*)(pA0 + 2 * QSTEP + k2);
                v3 = *(const float4*)(pA0 + 3 * QSTEP + k2);
                v4 = *(const float4*)(pB0 + 0 * QSTEP + k2);
                v5 = *(const float4*)(pB0 + 1 * QSTEP + k2);
            }

            #pragma unroll
            for (int jp = 0; jp < 2; jp++) {     // 2 k-step pairs (each 32 f16)
                uint32_t aF[2][2][4];
                #pragma unroll
                for (int i = 0; i < 2; i++)
                    #pragma unroll
                    for (int js = 0; js < 2; js++)
                        ldsm_x4(aF[i][js], aAddr + stOff
                                + (uint32_t)(i * 16 * PITCH_BY + jp * 64 + js * 32));

                uint32_t bF[2][4];
                ldsm_x4(bF[0], bAddr + stOff + (uint32_t)(jp * 64));
                #pragma unroll
                for (int tt = 0; tt < 8; tt++) {
                    if (tt < 7)
                        ldsm_x4(bF[(tt + 1) & 1], bAddr + stOff
                                + (uint32_t)((tt + 1) * 8 * PITCH_BY + jp * 64));
                    const uint32_t* bf = bF[tt & 1];
                    mma_f16(acc[0][tt], aF[0][0], bf);       // k-step 2jp
                    mma_f16(acc[1][tt], aF[1][0], bf);
                    mma_f16(acc[0][tt], aF[0][1], bf + 2);   // k-step 2jp+1
                    mma_f16(acc[1][tt], aF[1][1], bf + 2);
                }

                if (jp == 0 && more) {
                    *(uint2*)(smem + nbU32 + sA0 + 0 * 32 * PITCH_U) = cvt4h(v0);
                    *(uint2*)(smem + nbU32 + sA0 + 1 * 32 * PITCH_U) = cvt4h(v1);
                    *(uint2*)(smem + nbU32 + sA0 + 2 * 32 * PITCH_U) = cvt4h(v2);
                    *(uint2*)(smem + nbU32 + sA0 + 3 * 32 * PITCH_U) = cvt4h(v3);
                    *(uint2*)(smem + nbU32 + sB0 + 0 * 32 * PITCH_U) = cvt4h(v4);
                    *(uint2*)(smem + nbU32 + sB0 + 1 * 32 * PITCH_U) = cvt4h(v5);
                    v0 = *(const float4*)(pB0 + 2 * QSTEP + k2);
                    v1 = *(const float4*)(pB0 + 3 * QSTEP + k2);
                    v2 = *(const float4*)(pB0 + 4 * QSTEP + k2);
                    v3 = *(const float4*)(pB0 + 5 * QSTEP + k2);
                    v4 = *(const float4*)(pB0 + 6 * QSTEP + k2);
                    v5 = *(const float4*)(pB0 + 7 * QSTEP + k2);
                }
            }

            if (more) {
                *(uint2*)(smem + nbU32 + sB0 + 2 * 32 * PITCH_U) = cvt4h(v0);
                *(uint2*)(smem + nbU32 + sB0 + 3 * 32 * PITCH_U) = cvt4h(v1);
                *(uint2*)(smem + nbU32 + sB0 + 4 * 32 * PITCH_U) = cvt4h(v2);
                *(uint2*)(smem + nbU32 + sB0 + 5 * 32 * PITCH_U) = cvt4h(v3);
                *(uint2*)(smem + nbU32 + sB0 + 6 * 32 * PITCH_U) = cvt4h(v4);
                *(uint2*)(smem + nbU32 + sB0 + 7 * 32 * PITCH_U) = cvt4h(v5);
            }
            cs = (cs == 2) ? 0 : cs + 1;
            __syncthreads();   // one barrier per chunk (unconditional)
        }

        // ------ flush partial for this segment ------
        float* op = g_part + ((size_t)ordinal * MTOT + (size_t)t * 128) * NHID;
        #pragma unroll
        for (int i = 0; i < 2; i++) {
            #pragma unroll
            for (int tt = 0; tt < 8; tt++) {
                int row = mw + i * 16 + lr;
                int col = nw + tt * 8 + 2 * lc;
                float2 w0 = make_float2(acc[i][tt][0], acc[i][tt][1]);
                float2 w1 = make_float2(acc[i][tt][2], acc[i][tt][3]);
                *(float2*)(op + (size_t)row * NHID + col) = w0;
                *(float2*)(op + (size_t)(row + 8) * NHID + col) = w1;
            }
        }

        g0 = seg_end;
    }
}

// =====================================================================
// Kernel 2: fixed 6-slot reduce + bias + relu + 3-layer MLP tail
// 256 blocks x 512 threads, 8 batch rows per block.
// Layer 1 split: warp w -> row (w&7), j-half (w>>3); partials combined
// through smem. smem ~91KB -> 2 blocks/SM co-resident.
// =====================================================================
__global__ void __launch_bounds__(512) nnue_tail(
    const float* __restrict__ b_in,
    const float* __restrict__ W_h1, const float* __restrict__ b_h1,
    const float* __restrict__ W_h2, const float* __restrict__ b_h2,
    const float* __restrict__ W_out, const float* __restrict__ b_out,
    float* __restrict__ out)
{
    extern __shared__ float smem_t[];
    float* Wh1T = smem_t;                    // [512][33]
    float* c_sm = Wh1T + 512 * 33;           // [8][512]
    float* Wh2T = c_sm + 8 * 512;            // [32][33]
    float* x1p  = Wh2T + 32 * 33;            // [16][32] layer-1 partials
    float* x1s  = x1p + 16 * 32;             // [8][32]

    const int tid = threadIdx.x;
    const int row0 = blockIdx.x * 8;         // 0..2040

    for (int i = tid; i < 512 * 32; i += 512) {
        int o = i >> 9, j = i & 511;
        Wh1T[j * 33 + o] = W_h1[i];
    }
    for (int i = tid; i < 32 * 32; i += 512) {   // 1024 elems, 2 iters
        int o = i >> 5, j = i & 31;
        Wh2T[j * 33 + o] = W_h2[i];
    }
    // combined = [relu(wh), relu(bh)]: fixed 6-slot reduce (unwritten slots
    // are guaranteed-zero __device__ memory) -> 6 independent loads in flight
    for (int e = tid; e < 8 * 512; e += 512) {
        int rs = e >> 9, j = e & 511;
        int col = j & 255;
        int m = (j < 256) ? (row0 + rs) : (2048 + row0 + rs);
        size_t base = (size_t)m * NHID + col;
        float p0 = g_part[0 * (size_t)MTOT * NHID + base];
        float p1 = g_part[1 * (size_t)MTOT * NHID + base];
        float p2 = g_part[2 * (size_t)MTOT * NHID + base];
        float p3 = g_part[3 * (size_t)MTOT * NHID + base];
        float p4 = g_part[4 * (size_t)MTOT * NHID + base];
        float p5 = g_part[5 * (size_t)MTOT * NHID + base];
        float v = b_in[col] + ((p0 + p1) + (p2 + p3)) + (p4 + p5);
        c_sm[e] = fmaxf(v, 0.0f);
    }
    __syncthreads();

    const int o    = tid & 31;
    const int w    = tid >> 5;       // 0..15
    const int r    = w & 7;          // batch row within block
    const int half = w >> 3;         // j-range half: 0 or 1

    // layer 1 (split): 256 js per warp, c loads vectorized
    {
        float a0 = 0.f, a1 = 0.f, a2 = 0.f, a3 = 0.f;
        const float* c = c_sm + r * 512 + half * 256;
        #pragma unroll 2
        for (int j = 0; j < 256; j += 4) {
            float4 cv = *(const float4*)(c + j);
            int jw = half * 256 + j;
            a0 = fmaf(cv.x, Wh1T[(jw + 0) * 33 + o], a0);
            a1 = fmaf(cv.y, Wh1T[(jw + 1) * 33 + o], a1);
            a2 = fmaf(cv.z, Wh1T[(jw + 2) * 33 + o], a2);
            a3 = fmaf(cv.w, Wh1T[(jw + 3) * 33 + o], a3);
        }
        x1p[(half * 8 + r) * 32 + o] = (a0 + a1) + (a2 + a3);
    }
    __syncthreads();

    if (w < 8) {   // warps 0-7: combine halves, layer 2, output
        float x1 = fmaxf(x1p[r * 32 + o] + x1p[(8 + r) * 32 + o] + b_h1[o], 0.0f);
        x1s[r * 32 + o] = x1;
        __syncwarp();

        // layer 2: [32, 32]
        float acc2 = b_h2[o];
        #pragma unroll
        for (int j = 0; j < 32; j++)
            acc2 = fmaf(x1s[r * 32 + j], Wh2T[j * 33 + o], acc2);
        float x2 = fmaxf(acc2, 0.0f);

        // output: dot + warp reduce
        float y = x2 * W_out[o];
        #pragma unroll
        for (int d = 16; d > 0; d >>= 1)
            y += __shfl_xor_sync(0xFFFFFFFF, y, d);
        if (o == 0)
            out[row0 + r] = y + b_out[0];
    }
}

// =====================================================================
extern "C" void kernel_launch(void* const* d_in, const int* in_sizes, int n_in,
                              void* d_out, int out_size) {
    const float* wf    = (const float*)d_in[0];
    const float* bfeat = (const float*)d_in[1];
    const float* W_in  = (const float*)d_in[2];
    const float* b_in  = (const float*)d_in[3];
    const float* W_h1  = (const float*)d_in[4];
    const float* b_h1  = (const float*)d_in[5];
    const float* W_h2  = (const float*)d_in[6];
    const float* b_h2  = (const float*)d_in[7];
    const float* W_out = (const float*)d_in[8];
    const float* b_out = (const float*)d_in[9];
    float* out = (float*)d_out;

    cudaFuncSetAttribute(nnue_gemm, cudaFuncAttributeMaxDynamicSharedMemorySize, GEMM_SMEM);
    cudaFuncSetAttribute(nnue_tail, cudaFuncAttributeMaxDynamicSharedMemorySize, TAIL_SMEM);

    nnue_gemm<<<NCTAS, 512, GEMM_SMEM>>>(wf, bfeat, W_in);
    nnue_tail<<<256, 512, TAIL_SMEM>>>(b_in, W_h1, b_h1, W_h2, b_h2, W_out, b_out, out);
}

// round 15
// speedup vs baseline: 1.2496x; 1.0626x over previous
#include <cuda_runtime.h>
#include <cuda_fp16.h>
#include <stdint.h>

// ---------------- problem constants ----------------
#define KDIM    41024
#define NHID    256
#define MTOT    4096          // 2048 white + 2048 black
#define NTILES  32            // m-tiles of 128 rows
#define CPT     641           // BK64 chunks per m-tile (41024/64)
#define TOTCH   (NTILES * CPT)  // 20512
#define NCTAS   148
#define WCHUNK  139           // ceil(20512/148)
#define NSLOTS  6

// GEMM tile: BM=128, BN=256, BK=64 (f16), 512 threads, double-buffered
#define BK          64
#define PITCH_U     36        // u32 per row: 32 data (64 f16) + 4 pad
#define PITCH_BY    144
#define A_U32       (128 * PITCH_U)            // 4608
#define B_U32       (256 * PITCH_U)            // 9216
#define STAGE_U32   (A_U32 + B_U32)            // 13824
#define STAGE_BYTES (STAGE_U32 * 4)            // 55296
#define A_BYTES     (A_U32 * 4)                // 18432
#define GEMM_SMEM   (2 * STAGE_BYTES)          // 110592
// tail smem: Wh1T[512*33] + c_sm[8*512] + Wh2T[32*33] + x1p[16*32] + x1s[8*32]
#define TAIL_SMEM   ((512*33 + 8*512 + 32*33 + 16*32 + 8*32) * 4)  // ~91KB

// partial slots: [6][4096][256] fp32 = 25.2MB static scratch.
// Zero-initialized at module load; slots >= cnt(tile) are NEVER written,
// so they remain zero across all launches -> fixed 6-way reduce is exact.
__device__ float g_part[(size_t)NSLOTS * MTOT * NHID];

// ---------------- helpers ----------------
__device__ __forceinline__ uint32_t f2h2(float lo, float hi) {
    uint32_t r; asm("cvt.rn.f16x2.f32 %0, %1, %2;" : "=r"(r) : "f"(hi), "f"(lo)); return r;
}
__device__ __forceinline__ uint2 cvt4h(float4 v) {
    uint2 o; o.x = f2h2(v.x, v.y); o.y = f2h2(v.z, v.w); return o;
}
__device__ __forceinline__ void mma_f16(float* c, const uint32_t* a, const uint32_t* b) {
    asm volatile(
        "mma.sync.aligned.m16n8k16.row.col.f32.f16.f16.f32 "
        "{%0,%1,%2,%3}, {%4,%5,%6,%7}, {%8,%9}, {%0,%1,%2,%3};"
        : "+f"(c[0]), "+f"(c[1]), "+f"(c[2]), "+f"(c[3])
        : "r"(a[0]), "r"(a[1]), "r"(a[2]), "r"(a[3]), "r"(b[0]), "r"(b[1]));
}
__device__ __forceinline__ void ldsm_x4(uint32_t* r, uint32_t addr) {
    asm volatile("ldmatrix.sync.aligned.m8n8.x4.shared.b16 {%0,%1,%2,%3}, [%4];"
        : "=r"(r[0]), "=r"(r[1]), "=r"(r[2]), "=r"(r[3]) : "r"(addr));
}

// =====================================================================
// Kernel 1: flat-balanced GEMM (R12 structure — empirically optimal).
// 148 CTAs; CTA c covers global chunk range [139c, 139c+139). A range
// spans <=2 m-tiles; per tile-segment the CTA accumulates and flushes a
// partial to slot=ordinal-in-tile. 512 threads (16 warps, 4x4).
// Per warp per BK=64 chunk: 64 mma.m16n8k16. 2-stage double buffer,
// one barrier per chunk.
// =====================================================================
__global__ void __launch_bounds__(512, 1) nnue_gemm(
    const float* __restrict__ wf, const float* __restrict__ bfeat,
    const float* __restrict__ W_in)
{
    extern __shared__ uint32_t smem[];
    const uint32_t sbase = (uint32_t)__cvta_generic_to_shared(smem);

    const int tid = threadIdx.x;
    const int wid = tid >> 5;
    const int lane = tid & 31;
    const int lr = lane >> 2;       // 0..7
    const int lc = lane & 3;        // 0..3
    const int mw = (wid & 3) * 32;  // 4 m-warps
    const int nw = (wid >> 2) * 64; // 4 n-warps

    const int cta = blockIdx.x;
    int g0 = cta * WCHUNK;
    const int gEnd = min(g0 + WCHUNK, TOTCH);
    if (g0 >= gEnd) return;

    // ------ producer mapping: A 4 float4/thread, B 8 float4/thread ------
    const int pr = tid >> 4;        // 0..31 row base
    const int pc = tid & 15;        // float4 col 0..15 (64 floats per row)
    const int sA0 = pr * PITCH_U + 2 * pc;                 // u32 index
    const int sB0 = A_U32 + pr * PITCH_U + 2 * pc;
    const size_t QSTEP = (size_t)32 * KDIM;                // +32 rows per q
    const float* pB0 = W_in + (size_t)pr * KDIM + pc * 4;

    // ------ ldmatrix lane addresses ------
    const uint32_t aAddr = sbase + (uint32_t)(mw + (lane & 15)) * PITCH_BY
                         + (uint32_t)((lane >> 4) << 4);
    const uint32_t bAddr = sbase + A_BYTES + (uint32_t)(nw + (lane & 7)) * PITCH_BY
                         + (uint32_t)(((lane >> 3) & 3) << 4);

    float acc[2][8][4];

    // ---------------- segment loop (<=2 iterations) ----------------
    while (g0 < gEnd) {
        const int t = g0 / CPT;                       // m-tile
        const int seg_end = min(gEnd, (t + 1) * CPT);
        const int nch = seg_end - g0;
        const int kbase = g0 - t * CPT;               // first chunk within tile
        const int ordinal = cta - (t * CPT) / WCHUNK; // partial slot, 0..5

        const float* Xb = (t < 16) ? (wf + (size_t)t * 128 * KDIM)
                                   : (bfeat + (size_t)(t - 16) * 128 * KDIM);
        const float* pA0 = Xb + (size_t)pr * KDIM + pc * 4;

        #pragma unroll
        for (int i = 0; i < 2; i++)
            #pragma unroll
            for (int tt = 0; tt < 8; tt++)
                #pragma unroll
                for (int q = 0; q < 4; q++) acc[i][tt][q] = 0.0f;

        // prologue: fill stage 0 with chunk kbase
        {
            size_t k = (size_t)kbase * BK;
            #pragma unroll
            for (int q = 0; q < 4; q++)
                *(uint2*)(smem + sA0 + q * 32 * PITCH_U) = cvt4h(*(const float4*)(pA0 + q * QSTEP + k));
            #pragma unroll
            for (int q = 0; q < 8; q++)
                *(uint2*)(smem + sB0 + q * 32 * PITCH_U) = cvt4h(*(const float4*)(pB0 + q * QSTEP + k));
        }
        __syncthreads();

        for (int l = 0; l < nch; l++) {
            const int buf = l & 1;
            const bool more = (l + 1 < nch);
            const uint32_t stOff = (uint32_t)buf * STAGE_BYTES;
            const uint32_t nbU32 = (uint32_t)(buf ^ 1) * STAGE_U32;
            const size_t k2 = (size_t)(kbase + l + 1) * BK;

            // batch 1: A(4) + B(q=0,1) loads for next chunk
            float4 v0, v1, v2, v3, v4, v5;
            if (more) {
                v0 = *(const float4*)(pA0 + 0 * QSTEP + k2);
                v1 = *(const float4*)(pA0 + 1 * QSTEP + k2);
                v2 = *(const float4*)(pA0 + 2 * QSTEP + k2);
                v3 = *(const float4*)(pA0 + 3 * QSTEP + k2);
                v4 = *(const float4*)(pB0 + 0 * QSTEP + k2);
                v5 = *(const float4*)(pB0 + 1 * QSTEP + k2);
            }

            #pragma unroll
            for (int jp = 0; jp < 2; jp++) {     // 2 k-step pairs (each 32 f16)
                uint32_t aF[2][2][4];
                #pragma unroll
                for (int i = 0; i < 2; i++)
                    #pragma unroll
                    for (int js = 0; js < 2; js++)
                        ldsm_x4(aF[i][js], aAddr + stOff
                                + (uint32_t)(i * 16 * PITCH_BY + jp * 64 + js * 32));

                uint32_t bF[2][4];
                ldsm_x4(bF[0], bAddr + stOff + (uint32_t)(jp * 64));
                #pragma unroll
                for (int tt = 0; tt < 8; tt++) {
                    if (tt < 7)
                        ldsm_x4(bF[(tt + 1) & 1], bAddr + stOff
                                + (uint32_t)((tt + 1) * 8 * PITCH_BY + jp * 64));
                    const uint32_t* bf = bF[tt & 1];
                    mma_f16(acc[0][tt], aF[0][0], bf);       // k-step 2jp
                    mma_f16(acc[1][tt], aF[1][0], bf);
                    mma_f16(acc[0][tt], aF[0][1], bf + 2);   // k-step 2jp+1
                    mma_f16(acc[1][tt], aF[1][1], bf + 2);
                }

                if (jp == 0 && more) {
                    *(uint2*)(smem + nbU32 + sA0 + 0 * 32 * PITCH_U) = cvt4h(v0);
                    *(uint2*)(smem + nbU32 + sA0 + 1 * 32 * PITCH_U) = cvt4h(v1);
                    *(uint2*)(smem + nbU32 + sA0 + 2 * 32 * PITCH_U) = cvt4h(v2);
                    *(uint2*)(smem + nbU32 + sA0 + 3 * 32 * PITCH_U) = cvt4h(v3);
                    *(uint2*)(smem + nbU32 + sB0 + 0 * 32 * PITCH_U) = cvt4h(v4);
                    *(uint2*)(smem + nbU32 + sB0 + 1 * 32 * PITCH_U) = cvt4h(v5);
                    v0 = *(const float4*)(pB0 + 2 * QSTEP + k2);
                    v1 = *(const float4*)(pB0 + 3 * QSTEP + k2);
                    v2 = *(const float4*)(pB0 + 4 * QSTEP + k2);
                    v3 = *(const float4*)(pB0 + 5 * QSTEP + k2);
                    v4 = *(const float4*)(pB0 + 6 * QSTEP + k2);
                    v5 = *(const float4*)(pB0 + 7 * QSTEP + k2);
                }
            }

            if (more) {
                *(uint2*)(smem + nbU32 + sB0 + 2 * 32 * PITCH_U) = cvt4h(v0);
                *(uint2*)(smem + nbU32 + sB0 + 3 * 32 * PITCH_U) = cvt4h(v1);
                *(uint2*)(smem + nbU32 + sB0 + 4 * 32 * PITCH_U) = cvt4h(v2);
                *(uint2*)(smem + nbU32 + sB0 + 5 * 32 * PITCH_U) = cvt4h(v3);
                *(uint2*)(smem + nbU32 + sB0 + 6 * 32 * PITCH_U) = cvt4h(v4);
                *(uint2*)(smem + nbU32 + sB0 + 7 * 32 * PITCH_U) = cvt4h(v5);
            }
            __syncthreads();
        }

        // ------ flush partial for this segment ------
        float* op = g_part + ((size_t)ordinal * MTOT + (size_t)t * 128) * NHID;
        #pragma unroll
        for (int i = 0; i < 2; i++) {
            #pragma unroll
            for (int tt = 0; tt < 8; tt++) {
                int row = mw + i * 16 + lr;
                int col = nw + tt * 8 + 2 * lc;
                float2 w0 = make_float2(acc[i][tt][0], acc[i][tt][1]);
                float2 w1 = make_float2(acc[i][tt][2], acc[i][tt][3]);
                *(float2*)(op + (size_t)row * NHID + col) = w0;
                *(float2*)(op + (size_t)(row + 8) * NHID + col) = w1;
            }
        }

        g0 = seg_end;
    }
}

// =====================================================================
// Kernel 2: fixed 6-slot reduce + bias + relu + 3-layer MLP tail
// 256 blocks x 512 threads, 8 batch rows per block.
// Reduce phase fully float4-vectorized (12 LDG.128/thread).
// Layer 1 split: warp w -> row (w&7), j-half (w>>3); partials combined
// through smem. smem ~91KB -> 2 blocks/SM co-resident.
// =====================================================================
__global__ void __launch_bounds__(512) nnue_tail(
    const float* __restrict__ b_in,
    const float* __restrict__ W_h1, const float* __restrict__ b_h1,
    const float* __restrict__ W_h2, const float* __restrict__ b_h2,
    const float* __restrict__ W_out, const float* __restrict__ b_out,
    float* __restrict__ out)
{
    extern __shared__ float smem_t[];
    float* Wh1T = smem_t;                    // [512][33]
    float* c_sm = Wh1T + 512 * 33;           // [8][512]
    float* Wh2T = c_sm + 8 * 512;            // [32][33]
    float* x1p  = Wh2T + 32 * 33;            // [16][32] layer-1 partials
    float* x1s  = x1p + 16 * 32;             // [8][32]

    const int tid = threadIdx.x;
    const int row0 = blockIdx.x * 8;         // 0..2040

    // stage W_h1 transposed: float4 gmem loads, scattered smem stores
    for (int i4 = tid; i4 < 512 * 32 / 4; i4 += 512) {
        int i = i4 * 4;
        int o = i >> 9, j = i & 511;          // 4 consecutive j, same o
        float4 w = *(const float4*)(W_h1 + i);
        Wh1T[(j + 0) * 33 + o] = w.x;
        Wh1T[(j + 1) * 33 + o] = w.y;
        Wh1T[(j + 2) * 33 + o] = w.z;
        Wh1T[(j + 3) * 33 + o] = w.w;
    }
    for (int i = tid; i < 32 * 32; i += 512) {   // 1024 elems, 2 iters
        int o = i >> 5, j = i & 31;
        Wh2T[j * 33 + o] = W_h2[i];
    }
    // combined = [relu(wh), relu(bh)]: fixed 6-slot float4 reduce
    // (unwritten slots are guaranteed-zero __device__ memory)
    for (int e4 = tid; e4 < 8 * 128; e4 += 512) {     // 2 iterations
        int rs = e4 >> 7;                // row-slot 0..7
        int j4 = e4 & 127;               // float4 index within 512 floats
        int j  = j4 * 4;
        int col = j & 255;               // float4 never crosses 256 boundary
        int m = (j < 256) ? (row0 + rs) : (2048 + row0 + rs);
        const float4* base = (const float4*)(g_part + (size_t)m * NHID + col);
        const size_t S4 = (size_t)MTOT * NHID / 4;
        float4 p0 = base[0 * S4];
        float4 p1 = base[1 * S4];
        float4 p2 = base[2 * S4];
        float4 p3 = base[3 * S4];
        float4 p4 = base[4 * S4];
        float4 p5 = base[5 * S4];
        float4 bi = *(const float4*)(b_in + col);
        float4 v;
        v.x = bi.x + ((p0.x + p1.x) + (p2.x + p3.x)) + (p4.x + p5.x);
        v.y = bi.y + ((p0.y + p1.y) + (p2.y + p3.y)) + (p4.y + p5.y);
        v.z = bi.z + ((p0.z + p1.z) + (p2.z + p3.z)) + (p4.z + p5.z);
        v.w = bi.w + ((p0.w + p1.w) + (p2.w + p3.w)) + (p4.w + p5.w);
        v.x = fmaxf(v.x, 0.0f); v.y = fmaxf(v.y, 0.0f);
        v.z = fmaxf(v.z, 0.0f); v.w = fmaxf(v.w, 0.0f);
        *(float4*)(c_sm + rs * 512 + j) = v;
    }
    __syncthreads();

    const int o    = tid & 31;
    const int w    = tid >> 5;       // 0..15
    const int r    = w & 7;          // batch row within block
    const int half = w >> 3;         // j-range half: 0 or 1

    // layer 1 (split): 256 js per warp, c loads vectorized
    {
        float a0 = 0.f, a1 = 0.f, a2 = 0.f, a3 = 0.f;
        const float* c = c_sm + r * 512 + half * 256;
        #pragma unroll 2
        for (int j = 0; j < 256; j += 4) {
            float4 cv = *(const float4*)(c + j);
            int jw = half * 256 + j;
            a0 = fmaf(cv.x, Wh1T[(jw + 0) * 33 + o], a0);
            a1 = fmaf(cv.y, Wh1T[(jw + 1) * 33 + o], a1);
            a2 = fmaf(cv.z, Wh1T[(jw + 2) * 33 + o], a2);
            a3 = fmaf(cv.w, Wh1T[(jw + 3) * 33 + o], a3);
        }
        x1p[(half * 8 + r) * 32 + o] = (a0 + a1) + (a2 + a3);
    }
    __syncthreads();

    if (w < 8) {   // warps 0-7: combine halves, layer 2, output
        float x1 = fmaxf(x1p[r * 32 + o] + x1p[(8 + r) * 32 + o] + b_h1[o], 0.0f);
        x1s[r * 32 + o] = x1;
        __syncwarp();

        // layer 2: [32, 32]
        float acc2 = b_h2[o];
        #pragma unroll
        for (int j = 0; j < 32; j++)
            acc2 = fmaf(x1s[r * 32 + j], Wh2T[j * 33 + o], acc2);
        float x2 = fmaxf(acc2, 0.0f);

        // output: dot + warp reduce
        float y = x2 * W_out[o];
        #pragma unroll
        for (int d = 16; d > 0; d >>= 1)
            y += __shfl_xor_sync(0xFFFFFFFF, y, d);
        if (o == 0)
            out[row0 + r] = y + b_out[0];
    }
}

// =====================================================================
extern "C" void kernel_launch(void* const* d_in, const int* in_sizes, int n_in,
                              void* d_out, int out_size) {
    const float* wf    = (const float*)d_in[0];
    const float* bfeat = (const float*)d_in[1];
    const float* W_in  = (const float*)d_in[2];
    const float* b_in  = (const float*)d_in[3];
    const float* W_h1  = (const float*)d_in[4];
    const float* b_h1  = (const float*)d_in[5];
    const float* W_h2  = (const float*)d_in[6];
    const float* b_h2  = (const float*)d_in[7];
    const float* W_out = (const float*)d_in[8];
    const float* b_out = (const float*)d_in[9];
    float* out = (float*)d_out;

    cudaFuncSetAttribute(nnue_gemm, cudaFuncAttributeMaxDynamicSharedMemorySize, GEMM_SMEM);
    cudaFuncSetAttribute(nnue_tail, cudaFuncAttributeMaxDynamicSharedMemorySize, TAIL_SMEM);

    nnue_gemm<<<NCTAS, 512, GEMM_SMEM>>>(wf, bfeat, W_in);
    nnue_tail<<<256, 512, TAIL_SMEM>>>(b_in, W_h1, b_h1, W_h2, b_h2, W_out, b_out, out);
}

// round 16
// speedup vs baseline: 1.2572x; 1.0061x over previous
#include <cuda_runtime.h>
#include <cuda_fp16.h>
#include <stdint.h>

// ---------------- problem constants ----------------
#define KDIM    41024
#define NHID    256
#define MTOT    4096          // 2048 white + 2048 black
#define NTILES  32            // m-tiles of 128 rows
#define CPT     641           // BK64 chunks per m-tile (41024/64)
#define TOTCH   (NTILES * CPT)  // 20512
#define NCTAS   148
#define WCHUNK  139           // ceil(20512/148)
#define NSLOTS  6

// GEMM tile: BM=128, BN=256, BK=64 (f16), 512 threads, double-buffered
#define BK          64
#define PITCH_U     36        // u32 per row: 32 data (64 f16) + 4 pad
#define PITCH_BY    144
#define A_U32       (128 * PITCH_U)            // 4608
#define B_U32       (256 * PITCH_U)            // 9216
#define STAGE_U32   (A_U32 + B_U32)            // 13824
#define STAGE_BYTES (STAGE_U32 * 4)            // 55296
#define A_BYTES     (A_U32 * 4)                // 18432
#define GEMM_SMEM   (2 * STAGE_BYTES)          // 110592
// tail smem: Wh1T[512*33] + c_sm[8*512] + Wh2T[32*33] + x1p[16*32] + x1s[8*32]
#define TAIL_SMEM   ((512*33 + 8*512 + 32*33 + 16*32 + 8*32) * 4)  // ~91KB

// partial slots: [6][4096][256] fp32 = 25.2MB static scratch.
// Zero-initialized at module load; slots >= cnt(tile) are NEVER written,
// so they remain zero across all launches -> fixed 6-way reduce is exact.
__device__ float g_part[(size_t)NSLOTS * MTOT * NHID];

// ---------------- helpers ----------------
__device__ __forceinline__ uint32_t f2h2(float lo, float hi) {
    uint32_t r; asm("cvt.rn.f16x2.f32 %0, %1, %2;" : "=r"(r) : "f"(hi), "f"(lo)); return r;
}
__device__ __forceinline__ uint2 cvt4h(float4 v) {
    uint2 o; o.x = f2h2(v.x, v.y); o.y = f2h2(v.z, v.w); return o;
}
__device__ __forceinline__ void mma_f16(float* c, const uint32_t* a, const uint32_t* b) {
    asm volatile(
        "mma.sync.aligned.m16n8k16.row.col.f32.f16.f16.f32 "
        "{%0,%1,%2,%3}, {%4,%5,%6,%7}, {%8,%9}, {%0,%1,%2,%3};"
        : "+f"(c[0]), "+f"(c[1]), "+f"(c[2]), "+f"(c[3])
        : "r"(a[0]), "r"(a[1]), "r"(a[2]), "r"(a[3]), "r"(b[0]), "r"(b[1]));
}
__device__ __forceinline__ void ldsm_x4(uint32_t* r, uint32_t addr) {
    asm volatile("ldmatrix.sync.aligned.m8n8.x4.shared.b16 {%0,%1,%2,%3}, [%4];"
        : "=r"(r[0]), "=r"(r[1]), "=r"(r[2]), "=r"(r[3]) : "r"(addr));
}

// =====================================================================
// Kernel 1: flat-balanced GEMM (R12/R15 structure — empirically optimal).
// 148 CTAs; CTA c covers global chunk range [139c, 139c+139). A range
// spans <=2 m-tiles; per tile-segment the CTA accumulates and flushes a
// partial to slot=ordinal-in-tile. 512 threads (16 warps, 4x4).
// Per warp per BK=64 chunk: 64 mma.m16n8k16. 2-stage double buffer,
// one barrier per chunk.
// =====================================================================
__global__ void __launch_bounds__(512, 1) nnue_gemm(
    const float* __restrict__ wf, const float* __restrict__ bfeat,
    const float* __restrict__ W_in)
{
    extern __shared__ uint32_t smem[];
    const uint32_t sbase = (uint32_t)__cvta_generic_to_shared(smem);

    const int tid = threadIdx.x;
    const int wid = tid >> 5;
    const int lane = tid & 31;
    const int lr = lane >> 2;       // 0..7
    const int lc = lane & 3;        // 0..3
    const int mw = (wid & 3) * 32;  // 4 m-warps
    const int nw = (wid >> 2) * 64; // 4 n-warps

    const int cta = blockIdx.x;
    int g0 = cta * WCHUNK;
    const int gEnd = min(g0 + WCHUNK, TOTCH);
    if (g0 >= gEnd) return;

    // ------ producer mapping: A 4 float4/thread, B 8 float4/thread ------
    const int pr = tid >> 4;        // 0..31 row base
    const int pc = tid & 15;        // float4 col 0..15 (64 floats per row)
    const int sA0 = pr * PITCH_U + 2 * pc;                 // u32 index
    const int sB0 = A_U32 + pr * PITCH_U + 2 * pc;
    const size_t QSTEP = (size_t)32 * KDIM;                // +32 rows per q
    const float* pB0 = W_in + (size_t)pr * KDIM + pc * 4;

    // ------ ldmatrix lane addresses ------
    const uint32_t aAddr = sbase + (uint32_t)(mw + (lane & 15)) * PITCH_BY
                         + (uint32_t)((lane >> 4) << 4);
    const uint32_t bAddr = sbase + A_BYTES + (uint32_t)(nw + (lane & 7)) * PITCH_BY
                         + (uint32_t)(((lane >> 3) & 3) << 4);

    float acc[2][8][4];

    // ---------------- segment loop (<=2 iterations) ----------------
    while (g0 < gEnd) {
        const int t = g0 / CPT;                       // m-tile
        const int seg_end = min(gEnd, (t + 1) * CPT);
        const int nch = seg_end - g0;
        const int kbase = g0 - t * CPT;               // first chunk within tile
        const int ordinal = cta - (t * CPT) / WCHUNK; // partial slot, 0..5

        const float* Xb = (t < 16) ? (wf + (size_t)t * 128 * KDIM)
                                   : (bfeat + (size_t)(t - 16) * 128 * KDIM);
        const float* pA0 = Xb + (size_t)pr * KDIM + pc * 4;

        #pragma unroll
        for (int i = 0; i < 2; i++)
            #pragma unroll
            for (int tt = 0; tt < 8; tt++)
                #pragma unroll
                for (int q = 0; q < 4; q++) acc[i][tt][q] = 0.0f;

        // prologue: fill stage 0 with chunk kbase
        {
            size_t k = (size_t)kbase * BK;
            #pragma unroll
            for (int q = 0; q < 4; q++)
                *(uint2*)(smem + sA0 + q * 32 * PITCH_U) = cvt4h(*(const float4*)(pA0 + q * QSTEP + k));
            #pragma unroll
            for (int q = 0; q < 8; q++)
                *(uint2*)(smem + sB0 + q * 32 * PITCH_U) = cvt4h(*(const float4*)(pB0 + q * QSTEP + k));
        }
        __syncthreads();

        for (int l = 0; l < nch; l++) {
            const int buf = l & 1;
            const bool more = (l + 1 < nch);
            const uint32_t stOff = (uint32_t)buf * STAGE_BYTES;
            const uint32_t nbU32 = (uint32_t)(buf ^ 1) * STAGE_U32;
            const size_t k2 = (size_t)(kbase + l + 1) * BK;

            // batch 1: A(4) + B(q=0,1) loads for next chunk
            float4 v0, v1, v2, v3, v4, v5;
            if (more) {
                v0 = *(const float4*)(pA0 + 0 * QSTEP + k2);
                v1 = *(const float4*)(pA0 + 1 * QSTEP + k2);
                v2 = *(const float4*)(pA0 + 2 * QSTEP + k2);
                v3 = *(const float4*)(pA0 + 3 * QSTEP + k2);
                v4 = *(const float4*)(pB0 + 0 * QSTEP + k2);
                v5 = *(const float4*)(pB0 + 1 * QSTEP + k2);
            }

            #pragma unroll
            for (int jp = 0; jp < 2; jp++) {     // 2 k-step pairs (each 32 f16)
                uint32_t aF[2][2][4];
                #pragma unroll
                for (int i = 0; i < 2; i++)
                    #pragma unroll
                    for (int js = 0; js < 2; js++)
                        ldsm_x4(aF[i][js], aAddr + stOff
                                + (uint32_t)(i * 16 * PITCH_BY + jp * 64 + js * 32));

                uint32_t bF[2][4];
                ldsm_x4(bF[0], bAddr + stOff + (uint32_t)(jp * 64));
                #pragma unroll
                for (int tt = 0; tt < 8; tt++) {
                    if (tt < 7)
                        ldsm_x4(bF[(tt + 1) & 1], bAddr + stOff
                                + (uint32_t)((tt + 1) * 8 * PITCH_BY + jp * 64));
                    const uint32_t* bf = bF[tt & 1];
                    mma_f16(acc[0][tt], aF[0][0], bf);       // k-step 2jp
                    mma_f16(acc[1][tt], aF[1][0], bf);
                    mma_f16(acc[0][tt], aF[0][1], bf + 2);   // k-step 2jp+1
                    mma_f16(acc[1][tt], aF[1][1], bf + 2);
                }

                if (jp == 0 && more) {
                    *(uint2*)(smem + nbU32 + sA0 + 0 * 32 * PITCH_U) = cvt4h(v0);
                    *(uint2*)(smem + nbU32 + sA0 + 1 * 32 * PITCH_U) = cvt4h(v1);
                    *(uint2*)(smem + nbU32 + sA0 + 2 * 32 * PITCH_U) = cvt4h(v2);
                    *(uint2*)(smem + nbU32 + sA0 + 3 * 32 * PITCH_U) = cvt4h(v3);
                    *(uint2*)(smem + nbU32 + sB0 + 0 * 32 * PITCH_U) = cvt4h(v4);
                    *(uint2*)(smem + nbU32 + sB0 + 1 * 32 * PITCH_U) = cvt4h(v5);
                    v0 = *(const float4*)(pB0 + 2 * QSTEP + k2);
                    v1 = *(const float4*)(pB0 + 3 * QSTEP + k2);
                    v2 = *(const float4*)(pB0 + 4 * QSTEP + k2);
                    v3 = *(const float4*)(pB0 + 5 * QSTEP + k2);
                    v4 = *(const float4*)(pB0 + 6 * QSTEP + k2);
                    v5 = *(const float4*)(pB0 + 7 * QSTEP + k2);
                }
            }

            if (more) {
                *(uint2*)(smem + nbU32 + sB0 + 2 * 32 * PITCH_U) = cvt4h(v0);
                *(uint2*)(smem + nbU32 + sB0 + 3 * 32 * PITCH_U) = cvt4h(v1);
                *(uint2*)(smem + nbU32 + sB0 + 4 * 32 * PITCH_U) = cvt4h(v2);
                *(uint2*)(smem + nbU32 + sB0 + 5 * 32 * PITCH_U) = cvt4h(v3);
                *(uint2*)(smem + nbU32 + sB0 + 6 * 32 * PITCH_U) = cvt4h(v4);
                *(uint2*)(smem + nbU32 + sB0 + 7 * 32 * PITCH_U) = cvt4h(v5);
            }
            __syncthreads();
        }

        // ------ flush partial for this segment ------
        float* op = g_part + ((size_t)ordinal * MTOT + (size_t)t * 128) * NHID;
        #pragma unroll
        for (int i = 0; i < 2; i++) {
            #pragma unroll
            for (int tt = 0; tt < 8; tt++) {
                int row = mw + i * 16 + lr;
                int col = nw + tt * 8 + 2 * lc;
                float2 w0 = make_float2(acc[i][tt][0], acc[i][tt][1]);
                float2 w1 = make_float2(acc[i][tt][2], acc[i][tt][3]);
                *(float2*)(op + (size_t)row * NHID + col) = w0;
                *(float2*)(op + (size_t)(row + 8) * NHID + col) = w1;
            }
        }

        g0 = seg_end;
    }
}

// =====================================================================
// Kernel 2: fixed 6-slot reduce + bias + relu + 3-layer MLP tail
// 256 blocks x 512 threads, 8 batch rows per block.
// Phase-reordered: g_part loads issued BEFORE W_h1/W_h2 staging so the
// DRAM latency of the reduce is hidden under the staging work.
// Layer 1 split: warp w -> row (w&7), j-half (w>>3).
// __launch_bounds__(512, 2) pins regs <= 64 -> 2 blocks/SM (smem 91KB).
// =====================================================================
__global__ void __launch_bounds__(512, 2) nnue_tail(
    const float* __restrict__ b_in,
    const float* __restrict__ W_h1, const float* __restrict__ b_h1,
    const float* __restrict__ W_h2, const float* __restrict__ b_h2,
    const float* __restrict__ W_out, const float* __restrict__ b_out,
    float* __restrict__ out)
{
    extern __shared__ float smem_t[];
    float* Wh1T = smem_t;                    // [512][33]
    float* c_sm = Wh1T + 512 * 33;           // [8][512]
    float* Wh2T = c_sm + 8 * 512;            // [32][33]
    float* x1p  = Wh2T + 32 * 33;            // [16][32] layer-1 partials
    float* x1s  = x1p + 16 * 32;             // [8][32]

    const int tid = threadIdx.x;
    const int row0 = blockIdx.x * 8;         // 0..2040
    const size_t S4 = (size_t)MTOT * NHID / 4;   // 262144

    // ---- phase 1a: issue work-item A's reduce loads (6 slots + b_in) ----
    const int e4a = tid;                 // 0..511
    const int rsA = e4a >> 7;
    const int jA  = (e4a & 127) * 4;
    const int colA = jA & 255;
    const int mA = (jA < 256) ? (row0 + rsA) : (2048 + row0 + rsA);
    const float4* baseA = (const float4*)(g_part + (size_t)mA * NHID + colA);
    float4 a0 = baseA[0 * S4], a1 = baseA[1 * S4], a2 = baseA[2 * S4];
    float4 a3 = baseA[3 * S4], a4 = baseA[4 * S4], a5 = baseA[5 * S4];
    float4 biA = *(const float4*)(b_in + colA);

    // ---- phase 1b: stage W_h1 transposed (hides A's DRAM latency) ----
    for (int i4 = tid; i4 < 512 * 32 / 4; i4 += 512) {
        int i = i4 * 4;
        int o = i >> 9, j = i & 511;          // 4 consecutive j, same o
        float4 w = *(const float4*)(W_h1 + i);
        Wh1T[(j + 0) * 33 + o] = w.x;
        Wh1T[(j + 1) * 33 + o] = w.y;
        Wh1T[(j + 2) * 33 + o] = w.z;
        Wh1T[(j + 3) * 33 + o] = w.w;
    }

    // ---- phase 2a: issue work-item B's reduce loads ----
    const int e4b = tid + 512;           // 512..1023
    const int rsB = e4b >> 7;
    const int jB  = (e4b & 127) * 4;
    const int colB = jB & 255;
    const int mB = (jB < 256) ? (row0 + rsB) : (2048 + row0 + rsB);
    const float4* baseB = (const float4*)(g_part + (size_t)mB * NHID + colB);
    float4 b0 = baseB[0 * S4], b1 = baseB[1 * S4], b2 = baseB[2 * S4];
    float4 b3 = baseB[3 * S4], b4 = baseB[4 * S4], b5 = baseB[5 * S4];
    float4 biB = *(const float4*)(b_in + colB);

    // ---- phase 2b: stage W_h2 (hides B's latency) ----
    for (int i = tid; i < 32 * 32; i += 512) {   // 1024 elems, 2 iters
        int o = i >> 5, j = i & 31;
        Wh2T[j * 33 + o] = W_h2[i];
    }

    // ---- phase 3: combine + relu + store to c_sm ----
    {
        float4 v;
        v.x = biA.x + ((a0.x + a1.x) + (a2.x + a3.x)) + (a4.x + a5.x);
        v.y = biA.y + ((a0.y + a1.y) + (a2.y + a3.y)) + (a4.y + a5.y);
        v.z = biA.z + ((a0.z + a1.z) + (a2.z + a3.z)) + (a4.z + a5.z);
        v.w = biA.w + ((a0.w + a1.w) + (a2.w + a3.w)) + (a4.w + a5.w);
        v.x = fmaxf(v.x, 0.0f); v.y = fmaxf(v.y, 0.0f);
        v.z = fmaxf(v.z, 0.0f); v.w = fmaxf(v.w, 0.0f);
        *(float4*)(c_sm + rsA * 512 + jA) = v;
    }
    {
        float4 v;
        v.x = biB.x + ((b0.x + b1.x) + (b2.x + b3.x)) + (b4.x + b5.x);
        v.y = biB.y + ((b0.y + b1.y) + (b2.y + b3.y)) + (b4.y + b5.y);
        v.z = biB.z + ((b0.z + b1.z) + (b2.z + b3.z)) + (b4.z + b5.z);
        v.w = biB.w + ((b0.w + b1.w) + (b2.w + b3.w)) + (b4.w + b5.w);
        v.x = fmaxf(v.x, 0.0f); v.y = fmaxf(v.y, 0.0f);
        v.z = fmaxf(v.z, 0.0f); v.w = fmaxf(v.w, 0.0f);
        *(float4*)(c_sm + rsB * 512 + jB) = v;
    }
    __syncthreads();

    const int o    = tid & 31;
    const int w    = tid >> 5;       // 0..15
    const int r    = w & 7;          // batch row within block
    const int half = w >> 3;         // j-range half: 0 or 1

    // layer 1 (split): 256 js per warp, c loads vectorized
    {
        float q0 = 0.f, q1 = 0.f, q2 = 0.f, q3 = 0.f;
        const float* c = c_sm + r * 512 + half * 256;
        #pragma unroll 2
        for (int j = 0; j < 256; j += 4) {
            float4 cv = *(const float4*)(c + j);
            int jw = half * 256 + j;
            q0 = fmaf(cv.x, Wh1T[(jw + 0) * 33 + o], q0);
            q1 = fmaf(cv.y, Wh1T[(jw + 1) * 33 + o], q1);
            q2 = fmaf(cv.z, Wh1T[(jw + 2) * 33 + o], q2);
            q3 = fmaf(cv.w, Wh1T[(jw + 3) * 33 + o], q3);
        }
        x1p[(half * 8 + r) * 32 + o] = (q0 + q1) + (q2 + q3);
    }
    __syncthreads();

    if (w < 8) {   // warps 0-7: combine halves, layer 2, output
        float x1 = fmaxf(x1p[r * 32 + o] + x1p[(8 + r) * 32 + o] + b_h1[o], 0.0f);
        x1s[r * 32 + o] = x1;
        __syncwarp();

        // layer 2: [32, 32]
        float acc2 = b_h2[o];
        #pragma unroll
        for (int j = 0; j < 32; j++)
            acc2 = fmaf(x1s[r * 32 + j], Wh2T[j * 33 + o], acc2);
        float x2 = fmaxf(acc2, 0.0f);

        // output: dot + warp reduce
        float y = x2 * W_out[o];
        #pragma unroll
        for (int d = 16; d > 0; d >>= 1)
            y += __shfl_xor_sync(0xFFFFFFFF, y, d);
        if (o == 0)
            out[row0 + r] = y + b_out[0];
    }
}

// =====================================================================
extern "C" void kernel_launch(void* const* d_in, const int* in_sizes, int n_in,
                              void* d_out, int out_size) {
    const float* wf    = (const float*)d_in[0];
    const float* bfeat = (const float*)d_in[1];
    const float* W_in  = (const float*)d_in[2];
    const float* b_in  = (const float*)d_in[3];
    const float* W_h1  = (const float*)d_in[4];
    const float* b_h1  = (const float*)d_in[5];
    const float* W_h2  = (const float*)d_in[6];
    const float* b_h2  = (const float*)d_in[7];
    const float* W_out = (const float*)d_in[8];
    const float* b_out = (const float*)d_in[9];
    float* out = (float*)d_out;

    cudaFuncSetAttribute(nnue_gemm, cudaFuncAttributeMaxDynamicSharedMemorySize, GEMM_SMEM);
    cudaFuncSetAttribute(nnue_tail, cudaFuncAttributeMaxDynamicSharedMemorySize, TAIL_SMEM);

    nnue_gemm<<<NCTAS, 512, GEMM_SMEM>>>(wf, bfeat, W_in);
    nnue_tail<<<256, 512, TAIL_SMEM>>>(b_in, W_h1, b_h1, W_h2, b_h2, W_out, b_out, out);
}

// round 17
// speedup vs baseline: 1.2716x; 1.0114x over previous
#include <cuda_runtime.h>
#include <cuda_fp16.h>
#include <stdint.h>

// ---------------- problem constants ----------------
#define KDIM    41024
#define NHID    256
#define MTOT    4096          // 2048 white + 2048 black
#define NTILES  32            // m-tiles of 128 rows
#define CPT     641           // BK64 chunks per m-tile (41024/64)
#define TOTCH   (NTILES * CPT)  // 20512
#define NCTAS   148
#define WCHUNK  139           // ceil(20512/148)
#define NSLOTS  6

// GEMM tile: BM=128, BN=256, BK=64 (f16), 512 threads, double-buffered
#define BK          64
#define PITCH_U     36        // u32 per row: 32 data (64 f16) + 4 pad
#define PITCH_BY    144
#define A_U32       (128 * PITCH_U)            // 4608
#define B_U32       (256 * PITCH_U)            // 9216
#define STAGE_U32   (A_U32 + B_U32)            // 13824
#define STAGE_BYTES (STAGE_U32 * 4)            // 55296
#define A_BYTES     (A_U32 * 4)                // 18432
#define GEMM_SMEM   (2 * STAGE_BYTES)          // 110592
// tail smem: Wh1T[512*33] + c_sm[8*512] + Wh2T[32*33] + x1p[16*32] + x1s[8*32]
#define TAIL_SMEM   ((512*33 + 8*512 + 32*33 + 16*32 + 8*32) * 4)  // ~91KB

// partial slots: [6][4096][256] fp16 = 12.6MB static scratch.
// Zero-initialized at module load (+0.0 in fp16 is all-zero bits); slots
// >= cnt(tile) are NEVER written, so they remain zero across all launches
// -> fixed 6-way reduce is exact.
__device__ __half g_part[(size_t)NSLOTS * MTOT * NHID];

// ---------------- helpers ----------------
__device__ __forceinline__ uint32_t f2h2(float lo, float hi) {
    uint32_t r; asm("cvt.rn.f16x2.f32 %0, %1, %2;" : "=r"(r) : "f"(hi), "f"(lo)); return r;
}
__device__ __forceinline__ uint2 cvt4h(float4 v) {
    uint2 o; o.x = f2h2(v.x, v.y); o.y = f2h2(v.z, v.w); return o;
}
__device__ __forceinline__ void mma_f16(float* c, const uint32_t* a, const uint32_t* b) {
    asm volatile(
        "mma.sync.aligned.m16n8k16.row.col.f32.f16.f16.f32 "
        "{%0,%1,%2,%3}, {%4,%5,%6,%7}, {%8,%9}, {%0,%1,%2,%3};"
        : "+f"(c[0]), "+f"(c[1]), "+f"(c[2]), "+f"(c[3])
        : "r"(a[0]), "r"(a[1]), "r"(a[2]), "r"(a[3]), "r"(b[0]), "r"(b[1]));
}
__device__ __forceinline__ void ldsm_x4(uint32_t* r, uint32_t addr) {
    asm volatile("ldmatrix.sync.aligned.m8n8.x4.shared.b16 {%0,%1,%2,%3}, [%4];"
        : "=r"(r[0]), "=r"(r[1]), "=r"(r[2]), "=r"(r[3]) : "r"(addr));
}

// =====================================================================
// Kernel 1: flat-balanced GEMM (R12/R15 structure — empirically optimal).
// 148 CTAs; CTA c covers global chunk range [139c, 139c+139). A range
// spans <=2 m-tiles; per tile-segment the CTA accumulates and flushes a
// partial (fp16) to slot=ordinal-in-tile. 512 threads (16 warps, 4x4).
// Per warp per BK=64 chunk: 64 mma.m16n8k16. 2-stage double buffer,
// one barrier per chunk.
// =====================================================================
__global__ void __launch_bounds__(512, 1) nnue_gemm(
    const float* __restrict__ wf, const float* __restrict__ bfeat,
    const float* __restrict__ W_in)
{
    extern __shared__ uint32_t smem[];
    const uint32_t sbase = (uint32_t)__cvta_generic_to_shared(smem);

    const int tid = threadIdx.x;
    const int wid = tid >> 5;
    const int lane = tid & 31;
    const int lr = lane >> 2;       // 0..7
    const int lc = lane & 3;        // 0..3
    const int mw = (wid & 3) * 32;  // 4 m-warps
    const int nw = (wid >> 2) * 64; // 4 n-warps

    const int cta = blockIdx.x;
    int g0 = cta * WCHUNK;
    const int gEnd = min(g0 + WCHUNK, TOTCH);
    if (g0 >= gEnd) return;

    // ------ producer mapping: A 4 float4/thread, B 8 float4/thread ------
    const int pr = tid >> 4;        // 0..31 row base
    const int pc = tid & 15;        // float4 col 0..15 (64 floats per row)
    const int sA0 = pr * PITCH_U + 2 * pc;                 // u32 index
    const int sB0 = A_U32 + pr * PITCH_U + 2 * pc;
    const size_t QSTEP = (size_t)32 * KDIM;                // +32 rows per q
    const float* pB0 = W_in + (size_t)pr * KDIM + pc * 4;

    // ------ ldmatrix lane addresses ------
    const uint32_t aAddr = sbase + (uint32_t)(mw + (lane & 15)) * PITCH_BY
                         + (uint32_t)((lane >> 4) << 4);
    const uint32_t bAddr = sbase + A_BYTES + (uint32_t)(nw + (lane & 7)) * PITCH_BY
                         + (uint32_t)(((lane >> 3) & 3) << 4);

    float acc[2][8][4];

    // ---------------- segment loop (<=2 iterations) ----------------
    while (g0 < gEnd) {
        const int t = g0 / CPT;                       // m-tile
        const int seg_end = min(gEnd, (t + 1) * CPT);
        const int nch = seg_end - g0;
        const int kbase = g0 - t * CPT;               // first chunk within tile
        const int ordinal = cta - (t * CPT) / WCHUNK; // partial slot, 0..5

        const float* Xb = (t < 16) ? (wf + (size_t)t * 128 * KDIM)
                                   : (bfeat + (size_t)(t - 16) * 128 * KDIM);
        const float* pA0 = Xb + (size_t)pr * KDIM + pc * 4;

        #pragma unroll
        for (int i = 0; i < 2; i++)
            #pragma unroll
            for (int tt = 0; tt < 8; tt++)
                #pragma unroll
                for (int q = 0; q < 4; q++) acc[i][tt][q] = 0.0f;

        // prologue: fill stage 0 with chunk kbase
        {
            size_t k = (size_t)kbase * BK;
            #pragma unroll
            for (int q = 0; q < 4; q++)
                *(uint2*)(smem + sA0 + q * 32 * PITCH_U) = cvt4h(*(const float4*)(pA0 + q * QSTEP + k));
            #pragma unroll
            for (int q = 0; q < 8; q++)
                *(uint2*)(smem + sB0 + q * 32 * PITCH_U) = cvt4h(*(const float4*)(pB0 + q * QSTEP + k));
        }
        __syncthreads();

        for (int l = 0; l < nch; l++) {
            const int buf = l & 1;
            const bool more = (l + 1 < nch);
            const uint32_t stOff = (uint32_t)buf * STAGE_BYTES;
            const uint32_t nbU32 = (uint32_t)(buf ^ 1) * STAGE_U32;
            const size_t k2 = (size_t)(kbase + l + 1) * BK;

            // batch 1: A(4) + B(q=0,1) loads for next chunk
            float4 v0, v1, v2, v3, v4, v5;
            if (more) {
                v0 = *(const float4*)(pA0 + 0 * QSTEP + k2);
                v1 = *(const float4*)(pA0 + 1 * QSTEP + k2);
                v2 = *(const float4*)(pA0 + 2 * QSTEP + k2);
                v3 = *(const float4*)(pA0 + 3 * QSTEP + k2);
                v4 = *(const float4*)(pB0 + 0 * QSTEP + k2);
                v5 = *(const float4*)(pB0 + 1 * QSTEP + k2);
            }

            #pragma unroll
            for (int jp = 0; jp < 2; jp++) {     // 2 k-step pairs (each 32 f16)
                uint32_t aF[2][2][4];
                #pragma unroll
                for (int i = 0; i < 2; i++)
                    #pragma unroll
                    for (int js = 0; js < 2; js++)
                        ldsm_x4(aF[i][js], aAddr + stOff
                                + (uint32_t)(i * 16 * PITCH_BY + jp * 64 + js * 32));

                uint32_t bF[2][4];
                ldsm_x4(bF[0], bAddr + stOff + (uint32_t)(jp * 64));
                #pragma unroll
                for (int tt = 0; tt < 8; tt++) {
                    if (tt < 7)
                        ldsm_x4(bF[(tt + 1) & 1], bAddr + stOff
                                + (uint32_t)((tt + 1) * 8 * PITCH_BY + jp * 64));
                    const uint32_t* bf = bF[tt & 1];
                    mma_f16(acc[0][tt], aF[0][0], bf);       // k-step 2jp
                    mma_f16(acc[1][tt], aF[1][0], bf);
                    mma_f16(acc[0][tt], aF[0][1], bf + 2);   // k-step 2jp+1
                    mma_f16(acc[1][tt], aF[1][1], bf + 2);
                }

                if (jp == 0 && more) {
                    *(uint2*)(smem + nbU32 + sA0 + 0 * 32 * PITCH_U) = cvt4h(v0);
                    *(uint2*)(smem + nbU32 + sA0 + 1 * 32 * PITCH_U) = cvt4h(v1);
                    *(uint2*)(smem + nbU32 + sA0 + 2 * 32 * PITCH_U) = cvt4h(v2);
                    *(uint2*)(smem + nbU32 + sA0 + 3 * 32 * PITCH_U) = cvt4h(v3);
                    *(uint2*)(smem + nbU32 + sB0 + 0 * 32 * PITCH_U) = cvt4h(v4);
                    *(uint2*)(smem + nbU32 + sB0 + 1 * 32 * PITCH_U) = cvt4h(v5);
                    v0 = *(const float4*)(pB0 + 2 * QSTEP + k2);
                    v1 = *(const float4*)(pB0 + 3 * QSTEP + k2);
                    v2 = *(const float4*)(pB0 + 4 * QSTEP + k2);
                    v3 = *(const float4*)(pB0 + 5 * QSTEP + k2);
                    v4 = *(const float4*)(pB0 + 6 * QSTEP + k2);
                    v5 = *(const float4*)(pB0 + 7 * QSTEP + k2);
                }
            }

            if (more) {
                *(uint2*)(smem + nbU32 + sB0 + 2 * 32 * PITCH_U) = cvt4h(v0);
                *(uint2*)(smem + nbU32 + sB0 + 3 * 32 * PITCH_U) = cvt4h(v1);
                *(uint2*)(smem + nbU32 + sB0 + 4 * 32 * PITCH_U) = cvt4h(v2);
                *(uint2*)(smem + nbU32 + sB0 + 5 * 32 * PITCH_U) = cvt4h(v3);
                *(uint2*)(smem + nbU32 + sB0 + 6 * 32 * PITCH_U) = cvt4h(v4);
                *(uint2*)(smem + nbU32 + sB0 + 7 * 32 * PITCH_U) = cvt4h(v5);
            }
            __syncthreads();
        }

        // ------ flush partial for this segment (fp16, rn-converted) ------
        __half* op = g_part + ((size_t)ordinal * MTOT + (size_t)t * 128) * NHID;
        #pragma unroll
        for (int i = 0; i < 2; i++) {
            #pragma unroll
            for (int tt = 0; tt < 8; tt++) {
                int row = mw + i * 16 + lr;
                int col = nw + tt * 8 + 2 * lc;
                uint32_t h01 = f2h2(acc[i][tt][0], acc[i][tt][1]);
                uint32_t h23 = f2h2(acc[i][tt][2], acc[i][tt][3]);
                *(uint32_t*)(op + (size_t)row * NHID + col) = h01;
                *(uint32_t*)(op + (size_t)(row + 8) * NHID + col) = h23;
            }
        }

        g0 = seg_end;
    }
}

// =====================================================================
// Kernel 2: fixed 6-slot fp16 reduce + bias + relu + 3-layer MLP tail
// 256 blocks x 512 threads, 8 batch rows per block.
// Reduce: ONE work item/thread (8 cols via uint4 = 8 halves), 6 LDG.128
// issued BEFORE W_h1/W_h2 staging (latency hidden under staging).
// Layer 1 split: warp w -> row (w&7), j-half (w>>3).
// __launch_bounds__(512, 2) pins regs <= 64 -> 2 blocks/SM (smem 91KB).
// =====================================================================
__global__ void __launch_bounds__(512, 2) nnue_tail(
    const float* __restrict__ b_in,
    const float* __restrict__ W_h1, const float* __restrict__ b_h1,
    const float* __restrict__ W_h2, const float* __restrict__ b_h2,
    const float* __restrict__ W_out, const float* __restrict__ b_out,
    float* __restrict__ out)
{
    extern __shared__ float smem_t[];
    float* Wh1T = smem_t;                    // [512][33]
    float* c_sm = Wh1T + 512 * 33;           // [8][512]
    float* Wh2T = c_sm + 8 * 512;            // [32][33]
    float* x1p  = Wh2T + 32 * 33;            // [16][32] layer-1 partials
    float* x1s  = x1p + 16 * 32;             // [8][32]

    const int tid = threadIdx.x;
    const int row0 = blockIdx.x * 8;         // 0..2040

    // ---- phase 1a: issue reduce loads (6 slots x uint4 = 8 halves each) ----
    const int rs = tid >> 6;                 // row-slot 0..7
    const int j8 = (tid & 63) * 8;           // col-group start within 512
    const int col = j8 & 255;                // 8-col group never crosses 256
    const int m = (j8 < 256) ? (row0 + rs) : (2048 + row0 + rs);
    const uint4* base = (const uint4*)(g_part + (size_t)m * NHID + col);
    const size_t S8 = (size_t)MTOT * NHID / 8;   // uint4 stride per slot
    uint4 p0 = base[0 * S8], p1 = base[1 * S8], p2 = base[2 * S8];
    uint4 p3 = base[3 * S8], p4 = base[4 * S8], p5 = base[5 * S8];
    float4 bi0 = *(const float4*)(b_in + col);
    float4 bi1 = *(const float4*)(b_in + col + 4);

    // ---- phase 1b: stage W_h1 transposed (hides reduce DRAM latency) ----
    for (int i4 = tid; i4 < 512 * 32 / 4; i4 += 512) {
        int i = i4 * 4;
        int o = i >> 9, j = i & 511;          // 4 consecutive j, same o
        float4 w = *(const float4*)(W_h1 + i);
        Wh1T[(j + 0) * 33 + o] = w.x;
        Wh1T[(j + 1) * 33 + o] = w.y;
        Wh1T[(j + 2) * 33 + o] = w.z;
        Wh1T[(j + 3) * 33 + o] = w.w;
    }
    // ---- phase 1c: stage W_h2 ----
    for (int i = tid; i < 32 * 32; i += 512) {   // 1024 elems, 2 iters
        int o = i >> 5, j = i & 31;
        Wh2T[j * 33 + o] = W_h2[i];
    }

    // ---- phase 2: combine 6 fp16 slots in fp32 + bias + relu -> c_sm ----
    {
        float a[8];
        a[0] = bi0.x; a[1] = bi0.y; a[2] = bi0.z; a[3] = bi0.w;
        a[4] = bi1.x; a[5] = bi1.y; a[6] = bi1.z; a[7] = bi1.w;
        const uint4* ps[6] = { &p0, &p1, &p2, &p3, &p4, &p5 };
        #pragma unroll
        for (int s = 0; s < 6; s++) {
            const uint32_t* u = (const uint32_t*)ps[s];
            #pragma unroll
            for (int q = 0; q < 4; q++) {
                __half2 h = *(const __half2*)&u[q];
                float2 f = __half22float2(h);
                a[q * 2 + 0] += f.x;
                a[q * 2 + 1] += f.y;
            }
        }
        float4 v0, v1;
        v0.x = fmaxf(a[0], 0.0f); v0.y = fmaxf(a[1], 0.0f);
        v0.z = fmaxf(a[2], 0.0f); v0.w = fmaxf(a[3], 0.0f);
        v1.x = fmaxf(a[4], 0.0f); v1.y = fmaxf(a[5], 0.0f);
        v1.z = fmaxf(a[6], 0.0f); v1.w = fmaxf(a[7], 0.0f);
        *(float4*)(c_sm + rs * 512 + j8)     = v0;
        *(float4*)(c_sm + rs * 512 + j8 + 4) = v1;
    }
    __syncthreads();

    const int o    = tid & 31;
    const int w    = tid >> 5;       // 0..15
    const int r    = w & 7;          // batch row within block
    const int half = w >> 3;         // j-range half: 0 or 1

    // layer 1 (split): 256 js per warp, c loads vectorized
    {
        float q0 = 0.f, q1 = 0.f, q2 = 0.f, q3 = 0.f;
        const float* c = c_sm + r * 512 + half * 256;
        #pragma unroll 2
        for (int j = 0; j < 256; j += 4) {
            float4 cv = *(const float4*)(c + j);
            int jw = half * 256 + j;
            q0 = fmaf(cv.x, Wh1T[(jw + 0) * 33 + o], q0);
            q1 = fmaf(cv.y, Wh1T[(jw + 1) * 33 + o], q1);
            q2 = fmaf(cv.z, Wh1T[(jw + 2) * 33 + o], q2);
            q3 = fmaf(cv.w, Wh1T[(jw + 3) * 33 + o], q3);
        }
        x1p[(half * 8 + r) * 32 + o] = (q0 + q1) + (q2 + q3);
    }
    __syncthreads();

    if (w < 8) {   // warps 0-7: combine halves, layer 2, output
        float x1 = fmaxf(x1p[r * 32 + o] + x1p[(8 + r) * 32 + o] + b_h1[o], 0.0f);
        x1s[r * 32 + o] = x1;
        __syncwarp();

        // layer 2: [32, 32]
        float acc2 = b_h2[o];
        #pragma unroll
        for (int j = 0; j < 32; j++)
            acc2 = fmaf(x1s[r * 32 + j], Wh2T[j * 33 + o], acc2);
        float x2 = fmaxf(acc2, 0.0f);

        // output: dot + warp reduce
        float y = x2 * W_out[o];
        #pragma unroll
        for (int d = 16; d > 0; d >>= 1)
            y += __shfl_xor_sync(0xFFFFFFFF, y, d);
        if (o == 0)
            out[row0 + r] = y + b_out[0];
    }
}

// =====================================================================
extern "C" void kernel_launch(void* const* d_in, const int* in_sizes, int n_in,
                              void* d_out, int out_size) {
    const float* wf    = (const float*)d_in[0];
    const float* bfeat = (const float*)d_in[1];
    const float* W_in  = (const float*)d_in[2];
    const float* b_in  = (const float*)d_in[3];
    const float* W_h1  = (const float*)d_in[4];
    const float* b_h1  = (const float*)d_in[5];
    const float* W_h2  = (const float*)d_in[6];
    const float* b_h2  = (const float*)d_in[7];
    const float* W_out = (const float*)d_in[8];
    const float* b_out = (const float*)d_in[9];
    float* out = (float*)d_out;

    cudaFuncSetAttribute(nnue_gemm, cudaFuncAttributeMaxDynamicSharedMemorySize, GEMM_SMEM);
    cudaFuncSetAttribute(nnue_tail, cudaFuncAttributeMaxDynamicSharedMemorySize, TAIL_SMEM);

    nnue_gemm<<<NCTAS, 512, GEMM_SMEM>>>(wf, bfeat, W_in);
    nnue_tail<<<256, 512, TAIL_SMEM>>>(b_in, W_h1, b_h1, W_h2, b_h2, W_out, b_out, out);
}